// round 14
// baseline (speedup 1.0000x reference)
#include <cuda_runtime.h>
#include <cuda_bf16.h>
#include <math.h>
#include <stdint.h>

#define B_    256
#define T_    100
#define IN_   784
#define H_    200
#define R_    4
#define N_    128
#define D_    40
#define NCLS  5
#define G4H   800
#define RD    160
#define MSTRIDE 41
#define RSTR  164

#define BPB   2
#define NBLK  (B_/BPB)
#define THREADS 512
#define CS    4

// ---------------- device scratch ----------------
__device__ float g_G[B_*T_*G4H];
__device__ float g_Wg4[H_*H_*4];
__device__ float g_Wka2[H_*RD*2];
__device__ float g_WrhT[RD*H_];

// ---------------- cluster helpers ----------------
__device__ __forceinline__ unsigned ctarank() {
    unsigned r; asm("mov.u32 %0, %%cluster_ctarank;" : "=r"(r)); return r;
}
__device__ __forceinline__ void bcast_all(void* p, float v) {
    unsigned a = (unsigned)__cvta_generic_to_shared(p);
#pragma unroll
    for (int r = 0; r < CS; r++) {
        unsigned ra;
        asm("mapa.shared::cluster.u32 %0, %1, %2;" : "=r"(ra) : "r"(a), "r"(r));
        asm volatile("st.shared::cluster.f32 [%0], %1;" :: "r"(ra), "f"(v));
    }
}
__device__ __forceinline__ void st_rank(void* p, float v, int r) {
    unsigned a = (unsigned)__cvta_generic_to_shared(p);
    unsigned ra;
    asm("mapa.shared::cluster.u32 %0, %1, %2;" : "=r"(ra) : "r"(a), "r"(r));
    asm volatile("st.shared::cluster.f32 [%0], %1;" :: "r"(ra), "f"(v));
}
#define CLUSTER_SYNC() do { \
    asm volatile("barrier.cluster.arrive.aligned;" ::: "memory"); \
    asm volatile("barrier.cluster.wait.aligned;"   ::: "memory"); \
} while (0)

// ---------------- weight repack ----------------
__global__ void prep_weights(const float* __restrict__ Whh,
                             const float* __restrict__ Wkey,
                             const float* __restrict__ Wadd,
                             const float* __restrict__ Wrh) {
    int i = blockIdx.x * 256 + threadIdx.x;
    if (i < 160000) {
        int k = i / 800, rem = i % 800, ii = rem >> 2, g = rem & 3;
        g_Wg4[i] = Whh[(g * 200 + ii) * 200 + k];
    } else if (i < 224000) {
        int z = i - 160000;
        int k = z / 320, rem = z % 320, j = rem >> 1, w = rem & 1;
        g_Wka2[z] = w ? Wadd[j * 200 + k] : Wkey[j * 200 + k];
    } else if (i < 256000) {
        int z = i - 224000; int k = z / 200, j = z % 200;
        g_WrhT[z] = Wrh[j * 160 + k];
    }
}

// ---------------- big input GEMM (R13, byte-identical): bf16 split-3 m16n8k16 ----------------
#define GTM 128
#define GTN 128
#define GTK 16
#define GSTR 136

#define MMA_BF16(D, A, B0, B1) \
    asm volatile("mma.sync.aligned.m16n8k16.row.col.f32.bf16.bf16.f32 " \
                 "{%0,%1,%2,%3}, {%4,%5,%6,%7}, {%8,%9}, {%0,%1,%2,%3};" \
                 : "+f"((D)[0]), "+f"((D)[1]), "+f"((D)[2]), "+f"((D)[3]) \
                 : "r"((A)[0]), "r"((A)[1]), "r"((A)[2]), "r"((A)[3]), \
                   "r"(B0), "r"(B1))

__global__ __launch_bounds__(256) void gemm_gates_x(
    const float* __restrict__ X, const float* __restrict__ Wih,
    const float* __restrict__ bih) {
    __shared__ uint32_t Ah[8][GSTR], Al[8][GSTR];
    __shared__ uint32_t Bh[8][GSTR], Bl[8][GSTR];

    const int tid = threadIdx.x;
    const int m0 = blockIdx.y * GTM;
    const int n0 = blockIdx.x * GTN;
    const int wid = tid >> 5, lane = tid & 31;
    const int g = lane >> 2, l = lane & 3;
    const int wm = (wid >> 1) * 32;
    const int wn = (wid & 1) * 64;

    float d[2][8][4];
#pragma unroll
    for (int mf = 0; mf < 2; mf++)
#pragma unroll
        for (int nf = 0; nf < 8; nf++)
#pragma unroll
            for (int q = 0; q < 4; q++) d[mf][nf][q] = 0.f;

    const int ar = tid >> 1, ac = (tid & 1) * 8, ac2 = (tid & 1) * 4;
    const float* Asrc = X + (size_t)(m0 + ar) * IN_ + ac;
    const bool bvalid = (n0 + ar) < G4H;
    const float* Bsrc = bvalid ? (Wih + (size_t)(n0 + ar) * IN_ + ac) : nullptr;

    for (int kt = 0; kt < IN_; kt += GTK) {
        __syncthreads();
        {
            float4 v0 = *(const float4*)(Asrc + kt);
            float4 v1 = *(const float4*)(Asrc + kt + 4);
            float av[8] = {v0.x,v0.y,v0.z,v0.w,v1.x,v1.y,v1.z,v1.w};
            float4 w0 = make_float4(0.f,0.f,0.f,0.f), w1 = w0;
            if (bvalid) { w0 = *(const float4*)(Bsrc + kt); w1 = *(const float4*)(Bsrc + kt + 4); }
            float bv[8] = {w0.x,w0.y,w0.z,w0.w,w1.x,w1.y,w1.z,w1.w};
#pragma unroll
            for (int p = 0; p < 4; p++) {
                __nv_bfloat162 h = __floats2bfloat162_rn(av[2*p], av[2*p+1]);
                float r0 = __bfloat162float(h.x), r1 = __bfloat162float(h.y);
                __nv_bfloat162 lo = __floats2bfloat162_rn(av[2*p] - r0, av[2*p+1] - r1);
                Ah[ac2 + p][ar] = *(const uint32_t*)&h;
                Al[ac2 + p][ar] = *(const uint32_t*)&lo;
                __nv_bfloat162 hb = __floats2bfloat162_rn(bv[2*p], bv[2*p+1]);
                float s0 = __bfloat162float(hb.x), s1 = __bfloat162float(hb.y);
                __nv_bfloat162 lb = __floats2bfloat162_rn(bv[2*p] - s0, bv[2*p+1] - s1);
                Bh[ac2 + p][ar] = *(const uint32_t*)&hb;
                Bl[ac2 + p][ar] = *(const uint32_t*)&lb;
            }
        }
        __syncthreads();

        uint32_t ah[2][4], al_[2][4];
#pragma unroll
        for (int mf = 0; mf < 2; mf++) {
            int base = wm + 16 * mf;
            ah[mf][0]  = Ah[l][base + g];
            ah[mf][1]  = Ah[l][base + g + 8];
            ah[mf][2]  = Ah[l + 4][base + g];
            ah[mf][3]  = Ah[l + 4][base + g + 8];
            al_[mf][0] = Al[l][base + g];
            al_[mf][1] = Al[l][base + g + 8];
            al_[mf][2] = Al[l + 4][base + g];
            al_[mf][3] = Al[l + 4][base + g + 8];
        }
#pragma unroll
        for (int nf = 0; nf < 8; nf++) {
            int nb = wn + 8 * nf;
            uint32_t bh0 = Bh[l][nb + g];
            uint32_t bh1 = Bh[l + 4][nb + g];
            uint32_t bl0 = Bl[l][nb + g];
            uint32_t bl1 = Bl[l + 4][nb + g];
#pragma unroll
            for (int mf = 0; mf < 2; mf++) {
                MMA_BF16(d[mf][nf], ah[mf],  bh0, bh1);
                MMA_BF16(d[mf][nf], al_[mf], bh0, bh1);
                MMA_BF16(d[mf][nf], ah[mf],  bl0, bl1);
            }
        }
    }

#pragma unroll
    for (int mf = 0; mf < 2; mf++) {
#pragma unroll
        for (int nf = 0; nf < 8; nf++) {
            int col = n0 + wn + 8 * nf + 2 * l;
            if (col < G4H) {
                float b0 = bih[col], b1 = bih[col + 1];
                int row0 = m0 + wm + 16 * mf + g;
                float2 o0 = make_float2(d[mf][nf][0] + b0, d[mf][nf][1] + b1);
                float2 o1 = make_float2(d[mf][nf][2] + b0, d[mf][nf][3] + b1);
                *(float2*)&g_G[(size_t)row0 * G4H + col]       = o0;
                *(float2*)&g_G[(size_t)(row0 + 8) * G4H + col] = o1;
            }
        }
    }
}

// ---------------- recurrent kernel ----------------
struct __align__(16) BS {
    float M[N_ * MSTRIDE];
    float r[RD];
    float key[RD];
    float add[RD];
    float wr[R_ * N_];
    float wu[N_];
    float wwsum[N_];
    float Ksm[R_ * N_];
    float m2[N_];
    float wlu[N_];
    float outh[NCLS];
    float key2[R_];
    float sig;
    float pad_[2];
};
#define BSF (sizeof(BS)/4)

#define OFF_SWRH   (2*BSF)
#define OFF_HPRE   (OFF_SWRH + 8000)    // hpreT[k=200][b=8]
#define OFF_HT     (OFF_HPRE + 1600)    // htT[k=200][b=8]
#define OFF_RALL   (OFF_HT   + 1600)
#define OFF_CSL    (OFF_RALL + 1312)
#define OFF_PBUF   (OFF_CSL  + 400)
#define OFF_SWKA   (OFF_PBUF + 12800)   // sWka float2[k=200][j=40] = 16000 floats
#define SMEM_FLOATS (OFF_SWKA + 16000)

__device__ __forceinline__ float sigmoidf_(float x) { return 1.f / (1.f + expf(-x)); }

__global__ __launch_bounds__(THREADS) __cluster_dims__(CS, 1, 1)
void mann_recurrent(
    const float* __restrict__ bkey, const float* __restrict__ badd,
    const float* __restrict__ Wsig, const float* __restrict__ bsig,
    const float* __restrict__ Who,  const float* __restrict__ bho,
    const float* __restrict__ Wro,  const float* __restrict__ bro,
    const float* __restrict__ brh,  const float* __restrict__ bhh,
    float* __restrict__ out) {
    extern __shared__ float smemf[];
    BS* S          = reinterpret_cast<BS*>(smemf);
    float* sWrh    = smemf + OFF_SWRH;
    float* hpreT   = smemf + OFF_HPRE;   // [k][8]
    float* htT     = smemf + OFF_HT;     // [k][8]
    float* rAll    = smemf + OFF_RALL;
    float* cSlice  = smemf + OFF_CSL;
    float* Pbuf    = smemf + OFF_PBUF;
    float2* sWka   = reinterpret_cast<float2*>(smemf + OFF_SWKA);  // [k][40]

    const int tid  = threadIdx.x;
    const int blk  = blockIdx.x;
    const int wid  = tid >> 5, lane = tid & 31;
    const unsigned rank = ctarank();
    const int bbase = (blk >> 2) * 8;

    for (int b = 0; b < BPB; b++) {
        BS& s = S[b];
        for (int i = tid; i < N_ * MSTRIDE; i += THREADS) s.M[i] = 0.f;
        for (int i = tid; i < RD; i += THREADS) s.r[i] = 0.f;
        for (int i = tid; i < R_ * N_; i += THREADS) s.wr[i] = 0.f;
        for (int i = tid; i < N_; i += THREADS) s.wu[i] = 0.f;
    }
    for (int i = tid; i < 8 * 200; i += THREADS) htT[i] = 0.f;
    for (int i = tid; i < 8 * RSTR; i += THREADS) rAll[i] = 0.f;
    for (int i = tid; i < 8 * 50; i += THREADS) cSlice[i] = 0.f;
    for (int idx = tid; idx < 160 * 50; idx += THREADS) {
        int k = idx / 50, i = idx % 50;
        sWrh[idx] = g_WrhT[k * 200 + 50 * rank + i];
    }
    // pin this CTA's key/add weight slice in SMEM (64 KB)
    for (int idx = tid; idx < 200 * 40; idx += THREADS) {
        int k = idx / 40, j = idx % 40;
        sWka[idx] = *(const float2*)&g_Wka2[k * 320 + (40 * rank + j) * 2];
    }
    __syncthreads();
    CLUSTER_SYNC();

    const int p_b = tid & 7;
    const int p_i = tid >> 3;
    const int jg1 = 50 * rank + ((p_i < 50) ? p_i : 0);
    const float brh_r = brh[jg1];
    const int ci = tid % 50;
    const int cb = tid / 50;
    const int jg = 50 * rank + ci;
    float bh0 = bhh[jg], bh1 = bhh[200 + jg], bh2 = bhh[400 + jg], bh3 = bhh[600 + jg];
    const int fj = tid % 40;
    const int fb = tid / 40;
    const int jgka = 40 * rank + fj;
    const float bkey_r = bkey[jgka], badd_r = badd[jgka];

    for (int t = 0; t < T_; t++) {
        float G0 = 0.f, G1 = 0.f, G2 = 0.f, G3 = 0.f;
        if (tid < 400) {
            const float* Gp = g_G + ((size_t)(bbase + cb) * T_ + t) * G4H;
            G0 = Gp[jg]; G1 = Gp[200 + jg]; G2 = Gp[400 + jg]; G3 = Gp[600 + jg];
        }

        // ---- phase 1: hpre GEMV | LRU | prev output ----
        if (tid < 400) {
            const float* rr = &rAll[p_b * RSTR];
            float acc = htT[jg1 * 8 + p_b] + brh_r;
#pragma unroll 8
            for (int k = 0; k < RD; k++) acc += rr[k] * sWrh[k * 50 + p_i];
            bcast_all(&hpreT[jg1 * 8 + p_b], acc);
        } else if (wid == 13 || wid == 14) {
            int b = wid - 13;
            unsigned long long kv[4];
            float wl[4];
#pragma unroll
            for (int q = 0; q < 4; q++) {
                int n = lane + 32 * q;
                unsigned u = __float_as_uint(S[b].wu[n]);
                u = (u & 0x80000000u) ? ~u : (u | 0x80000000u);
                kv[q] = ((unsigned long long)u << 32) | (unsigned)n;
                wl[q] = 0.f;
            }
#pragma unroll
            for (int ss = 0; ss < 4; ss++) {
                unsigned long long m = kv[0]; int qi = 0;
#pragma unroll
                for (int q = 1; q < 4; q++) if (kv[q] < m) { m = kv[q]; qi = q; }
                unsigned long long wm = m;
#pragma unroll
                for (int o = 16; o > 0; o >>= 1) {
                    unsigned long long x = __shfl_xor_sync(0xffffffffu, wm, o);
                    if (x < wm) wm = x;
                }
                if (m == wm) { wl[qi] = 1.f; kv[qi] = ~0ull; }
            }
#pragma unroll
            for (int q = 0; q < 4; q++) S[b].wlu[lane + 32 * q] = wl[q];
        } else if (wid == 15 && t > 0) {
            for (int p = 0; p < BPB * NCLS; p++) {
                int b = p / NCLS, cls = p % NCLS;
                const float* rr = S[b].r;
                float acc = 0.f;
#pragma unroll
                for (int k = lane; k < RD; k += 32) acc += rr[k] * Wro[cls * RD + k];
#pragma unroll
                for (int o = 16; o > 0; o >>= 1) acc += __shfl_down_sync(0xffffffffu, acc, o);
                if (lane == 0)
                    out[((size_t)(blk * BPB + b) * T_ + (t - 1)) * NCLS + cls] = acc + S[b].outh[cls];
            }
        }
        CLUSTER_SYNC();

        // ---- phase 2 GEMV: gates slice (vectorized h reads) ----
        if (tid < 400) {
            int i2 = tid % 50, ks = tid / 50;
            float ag[8][4];
#pragma unroll
            for (int b = 0; b < 8; b++)
#pragma unroll
                for (int g = 0; g < 4; g++) ag[b][g] = 0.f;
            const float4* W = reinterpret_cast<const float4*>(g_Wg4) + (50 * rank + i2);
            const float4* HP = reinterpret_cast<const float4*>(hpreT);
            int k0 = 25 * ks;
#pragma unroll 5
            for (int kk = 0; kk < 25; kk++) {
                int k = k0 + kk;
                float4 w = W[k * 200];
                float4 hA = HP[k * 2];
                float4 hB = HP[k * 2 + 1];
                float hv[8] = {hA.x, hA.y, hA.z, hA.w, hB.x, hB.y, hB.z, hB.w};
#pragma unroll
                for (int b = 0; b < 8; b++) {
                    float hb = hv[b];
                    ag[b][0] += w.x * hb; ag[b][1] += w.y * hb;
                    ag[b][2] += w.z * hb; ag[b][3] += w.w * hb;
                }
            }
#pragma unroll
            for (int b = 0; b < 8; b++)
#pragma unroll
                for (int g = 0; g < 4; g++)
                    Pbuf[(b * 4 + g) * 400 + ks * 50 + i2] = ag[b][g];
        }
        __syncthreads();

        // ---- phase 2b: combine + LSTM + h_t broadcast (transposed) ----
        if (tid < 400) {
            float s0 = G0 + bh0, s1 = G1 + bh1, s2 = G2 + bh2, s3 = G3 + bh3;
#pragma unroll
            for (int ks = 0; ks < 8; ks++) {
                s0 += Pbuf[(cb * 4 + 0) * 400 + ks * 50 + ci];
                s1 += Pbuf[(cb * 4 + 1) * 400 + ks * 50 + ci];
                s2 += Pbuf[(cb * 4 + 2) * 400 + ks * 50 + ci];
                s3 += Pbuf[(cb * 4 + 3) * 400 + ks * 50 + ci];
            }
            float ig = sigmoidf_(s0), fg = sigmoidf_(s1);
            float gg = tanhf(s2),    og = sigmoidf_(s3);
            float ct = fg * cSlice[cb * 50 + ci] + ig * gg;
            cSlice[cb * 50 + ci] = ct;
            float ht = og * tanhf(ct);
            bcast_all(&htT[jg * 8 + cb], ht);
        }
        CLUSTER_SYNC();

        // ---- phase 4 GEMV: key/add slice (SMEM weights, vectorized h) | sigma | outh ----
        if (tid < 320) {
            int j = tid % 40, ks = tid / 40;
            float ak[8], aa[8];
#pragma unroll
            for (int b = 0; b < 8; b++) { ak[b] = 0.f; aa[b] = 0.f; }
            const float4* HT = reinterpret_cast<const float4*>(htT);
            int k0 = 25 * ks;
#pragma unroll 5
            for (int kk = 0; kk < 25; kk++) {
                int k = k0 + kk;
                float2 w = sWka[k * 40 + j];
                float4 hA = HT[k * 2];
                float4 hB = HT[k * 2 + 1];
                float hv[8] = {hA.x, hA.y, hA.z, hA.w, hB.x, hB.y, hB.z, hB.w};
#pragma unroll
                for (int b = 0; b < 8; b++) {
                    ak[b] += w.x * hv[b]; aa[b] += w.y * hv[b];
                }
            }
#pragma unroll
            for (int b = 0; b < 8; b++) {
                Pbuf[(b * 2 + 0) * 320 + ks * 40 + j] = ak[b];
                Pbuf[(b * 2 + 1) * 320 + ks * 40 + j] = aa[b];
            }
        } else if (wid == 10 || wid == 11) {
            int b = wid - 10;
            int bb = rank * 2 + b;
            float p = 0.f;
            for (int k = lane; k < H_; k += 32) p += htT[k * 8 + bb] * Wsig[k];
#pragma unroll
            for (int o = 16; o > 0; o >>= 1) p += __shfl_xor_sync(0xffffffffu, p, o);
            if (lane == 0) S[b].sig = p + bsig[0];
        } else if (wid == 12 || wid == 13) {
            int b = wid - 12;
            int bb = rank * 2 + b;
            for (int cls = 0; cls < NCLS; cls++) {
                float acc = 0.f;
#pragma unroll
                for (int k = lane; k < H_; k += 32) acc += htT[k * 8 + bb] * Who[cls * H_ + k];
#pragma unroll
                for (int o = 16; o > 0; o >>= 1) acc += __shfl_down_sync(0xffffffffu, acc, o);
                if (lane == 0) S[b].outh[cls] = acc + bho[cls] + bro[cls];
            }
        }
        __syncthreads();

        // ---- phase 4b: combine + scatter key/add to owners ----
        if (tid < 320) {
            float vk = bkey_r, va = badd_r;
#pragma unroll
            for (int ks = 0; ks < 8; ks++) {
                vk += Pbuf[(fb * 2 + 0) * 320 + ks * 40 + fj];
                va += Pbuf[(fb * 2 + 1) * 320 + ks * 40 + fj];
            }
            int owner = fb >> 1, lb = fb & 1;
            st_rank(&S[lb].key[jgka], vk, owner);
            st_rank(&S[lb].add[jgka], va, owner);
        }
        CLUSTER_SYNC();

        // ---- fused p6+p7: M update + wwsum + m2 + raw cosine dots ----
        {
            int b = tid >> 8;
            int n = (tid >> 1) & 127;
            int dh = tid & 1;
            BS& s = S[b];
            float sg = s.sig, omsg = 1.f - sg;
            float wl = s.wlu[n];
            float w0 = sg * s.wr[n]       + omsg * wl;
            float w1 = sg * s.wr[128 + n] + omsg * wl;
            float w2 = sg * s.wr[256 + n] + omsg * wl;
            float w3 = sg * s.wr[384 + n] + omsg * wl;
            if (dh == 0) s.wwsum[n] = w0 + w1 + w2 + w3;
            float mv[20];
            float m2p = 0.f;
            int d0 = dh * 20;
#pragma unroll
            for (int dd = 0; dd < 20; dd++) {
                int d = d0 + dd;
                float v = s.M[n * MSTRIDE + d] * wl
                         + w0 * s.add[d] + w1 * s.add[40 + d]
                         + w2 * s.add[80 + d] + w3 * s.add[120 + d];
                s.M[n * MSTRIDE + d] = v;
                mv[dd] = v;
                m2p += v * v;
            }
            m2p += __shfl_xor_sync(0xffffffffu, m2p, 1);
            if (dh == 0) s.m2[n] = m2p;
            // raw dots (normalization deferred to softmax phase)
#pragma unroll
            for (int r = 0; r < 4; r++) {
                const float* kp = s.key + r * 40 + d0;
                float dp = 0.f;
#pragma unroll
                for (int dd = 0; dd < 20; dd++) dp += mv[dd] * kp[dd];
                dp += __shfl_xor_sync(0xffffffffu, dp, 1);
                if (dh == 0) s.Ksm[r * N_ + n] = dp;
            }
        }
        __syncthreads();

        // ---- phase 8: normalize + softmax over n (warp per (b,r)) ----
        if (wid < 8) {
            int b = wid >> 2, r = wid & 3;
            BS& s = S[b];
            // key2[r] computed in-warp
            float ke = s.key[r * 40 + lane];
            float p = ke * ke;
            if (lane < 8) { float k2 = s.key[r * 40 + 32 + lane]; p += k2 * k2; }
#pragma unroll
            for (int o = 16; o > 0; o >>= 1) p += __shfl_xor_sync(0xffffffffu, p, o);
            float v0 = s.Ksm[r * N_ + lane]      / sqrtf(p * s.m2[lane]      + 1e-6f);
            float v1 = s.Ksm[r * N_ + 32 + lane] / sqrtf(p * s.m2[32 + lane] + 1e-6f);
            float v2 = s.Ksm[r * N_ + 64 + lane] / sqrtf(p * s.m2[64 + lane] + 1e-6f);
            float v3 = s.Ksm[r * N_ + 96 + lane] / sqrtf(p * s.m2[96 + lane] + 1e-6f);
            float mx = fmaxf(fmaxf(v0, v1), fmaxf(v2, v3));
#pragma unroll
            for (int o = 16; o > 0; o >>= 1) mx = fmaxf(mx, __shfl_xor_sync(0xffffffffu, mx, o));
            float e0 = expf(v0 - mx), e1 = expf(v1 - mx), e2 = expf(v2 - mx), e3 = expf(v3 - mx);
            float su = e0 + e1 + e2 + e3;
#pragma unroll
            for (int o = 16; o > 0; o >>= 1) su += __shfl_xor_sync(0xffffffffu, su, o);
            float inv = 1.f / su;
            s.wr[r * N_ + lane]      = e0 * inv;
            s.wr[r * N_ + 32 + lane] = e1 * inv;
            s.wr[r * N_ + 64 + lane] = e2 * inv;
            s.wr[r * N_ + 96 + lane] = e3 * inv;
        }
        __syncthreads();

        // ---- phase 9: wu update ; phase 10: r_t = wr @ M + broadcast ----
        if (tid < 256) {
            int b = tid >> 7, n = tid & 127;
            BS& s = S[b];
            s.wu[n] = 0.95f * s.wu[n]
                    + (s.wr[n] + s.wr[128 + n] + s.wr[256 + n] + s.wr[384 + n])
                    + s.wwsum[n];
        }
        if (tid < 320) {
            int b = tid / 160, rd = tid % 160;
            int r = rd / 40, d = rd % 40;
            BS& s = S[b];
            const float* wrp = s.wr + r * N_;
            float dot = 0.f;
#pragma unroll 8
            for (int n = 0; n < N_; n++) dot += wrp[n] * s.M[n * MSTRIDE + d];
            s.r[rd] = dot;
            bcast_all(&rAll[(rank * 2 + b) * RSTR + rd], dot);
        }
        CLUSTER_SYNC();
    }

    // ---- final output (t = 99) ----
    if (wid == 15) {
        for (int p = 0; p < BPB * NCLS; p++) {
            int b = p / NCLS, cls = p % NCLS;
            const float* rr = S[b].r;
            float acc = 0.f;
#pragma unroll
            for (int k = lane; k < RD; k += 32) acc += rr[k] * Wro[cls * RD + k];
#pragma unroll
            for (int o = 16; o > 0; o >>= 1) acc += __shfl_down_sync(0xffffffffu, acc, o);
            if (lane == 0)
                out[((size_t)(blk * BPB + b) * T_ + (T_ - 1)) * NCLS + cls] = acc + S[b].outh[cls];
        }
    }
}

// ---------------- launch ----------------
extern "C" void kernel_launch(void* const* d_in, const int* in_sizes, int n_in,
                              void* d_out, int out_size) {
    const float* x    = (const float*)d_in[0];
    const float* Wkey = (const float*)d_in[1];
    const float* bkey = (const float*)d_in[2];
    const float* Wadd = (const float*)d_in[3];
    const float* badd = (const float*)d_in[4];
    const float* Wsig = (const float*)d_in[5];
    const float* bsig = (const float*)d_in[6];
    const float* Who  = (const float*)d_in[7];
    const float* bho  = (const float*)d_in[8];
    const float* Wro  = (const float*)d_in[9];
    const float* bro  = (const float*)d_in[10];
    const float* Wrh  = (const float*)d_in[11];
    const float* brh  = (const float*)d_in[12];
    const float* Wih  = (const float*)d_in[13];
    const float* bih  = (const float*)d_in[14];
    const float* Whh  = (const float*)d_in[15];
    const float* bhh  = (const float*)d_in[16];
    float* out = (float*)d_out;

    prep_weights<<<1000, 256>>>(Whh, Wkey, Wadd, Wrh);
    gemm_gates_x<<<dim3((G4H + GTN - 1) / GTN, B_ * T_ / GTM), 256>>>(x, Wih, bih);

    size_t shmem = (size_t)SMEM_FLOATS * 4;
    cudaFuncSetAttribute(mann_recurrent, cudaFuncAttributeMaxDynamicSharedMemorySize, (int)shmem);
    mann_recurrent<<<NBLK, THREADS, shmem>>>(bkey, badd, Wsig, bsig, Who, bho,
                                             Wro, bro, brh, bhh, out);
}

// round 15
// speedup vs baseline: 1.0106x; 1.0106x over previous
#include <cuda_runtime.h>
#include <cuda_bf16.h>
#include <math.h>
#include <stdint.h>

#define B_    256
#define T_    100
#define IN_   784
#define H_    200
#define R_    4
#define N_    128
#define D_    40
#define NCLS  5
#define G4H   800
#define RD    160
#define MSTRIDE 41
#define RSTR  164

#define BPB   2
#define NBLK  (B_/BPB)
#define THREADS 512
#define CS    4

// ---------------- device scratch ----------------
__device__ float g_G[B_*T_*G4H];
__device__ float g_Wg4[H_*H_*4];
__device__ float g_Wka2[H_*RD*2];
__device__ float g_WrhT[RD*H_];

// ---------------- cluster helpers ----------------
__device__ __forceinline__ unsigned ctarank() {
    unsigned r; asm("mov.u32 %0, %%cluster_ctarank;" : "=r"(r)); return r;
}
__device__ __forceinline__ void bcast_all(void* p, float v) {
    unsigned a = (unsigned)__cvta_generic_to_shared(p);
#pragma unroll
    for (int r = 0; r < CS; r++) {
        unsigned ra;
        asm("mapa.shared::cluster.u32 %0, %1, %2;" : "=r"(ra) : "r"(a), "r"(r));
        asm volatile("st.shared::cluster.f32 [%0], %1;" :: "r"(ra), "f"(v));
    }
}
__device__ __forceinline__ void st_rank(void* p, float v, int r) {
    unsigned a = (unsigned)__cvta_generic_to_shared(p);
    unsigned ra;
    asm("mapa.shared::cluster.u32 %0, %1, %2;" : "=r"(ra) : "r"(a), "r"(r));
    asm volatile("st.shared::cluster.f32 [%0], %1;" :: "r"(ra), "f"(v));
}
#define CLUSTER_SYNC() do { \
    asm volatile("barrier.cluster.arrive.aligned;" ::: "memory"); \
    asm volatile("barrier.cluster.wait.aligned;"   ::: "memory"); \
} while (0)

// ---------------- weight repack ----------------
__global__ void prep_weights(const float* __restrict__ Whh,
                             const float* __restrict__ Wkey,
                             const float* __restrict__ Wadd,
                             const float* __restrict__ Wrh) {
    int i = blockIdx.x * 256 + threadIdx.x;
    if (i < 160000) {
        int k = i / 800, rem = i % 800, ii = rem >> 2, g = rem & 3;
        g_Wg4[i] = Whh[(g * 200 + ii) * 200 + k];
    } else if (i < 224000) {
        int z = i - 160000;
        int k = z / 320, rem = z % 320, j = rem >> 1, w = rem & 1;
        g_Wka2[z] = w ? Wadd[j * 200 + k] : Wkey[j * 200 + k];
    } else if (i < 256000) {
        int z = i - 224000; int k = z / 200, j = z % 200;
        g_WrhT[z] = Wrh[j * 160 + k];
    }
}

// ---------------- big input GEMM (R13, byte-identical): bf16 split-3 m16n8k16 ----------------
#define GTM 128
#define GTN 128
#define GTK 16
#define GSTR 136

#define MMA_BF16(D, A, B0, B1) \
    asm volatile("mma.sync.aligned.m16n8k16.row.col.f32.bf16.bf16.f32 " \
                 "{%0,%1,%2,%3}, {%4,%5,%6,%7}, {%8,%9}, {%0,%1,%2,%3};" \
                 : "+f"((D)[0]), "+f"((D)[1]), "+f"((D)[2]), "+f"((D)[3]) \
                 : "r"((A)[0]), "r"((A)[1]), "r"((A)[2]), "r"((A)[3]), \
                   "r"(B0), "r"(B1))

__global__ __launch_bounds__(256) void gemm_gates_x(
    const float* __restrict__ X, const float* __restrict__ Wih,
    const float* __restrict__ bih) {
    __shared__ uint32_t Ah[8][GSTR], Al[8][GSTR];
    __shared__ uint32_t Bh[8][GSTR], Bl[8][GSTR];

    const int tid = threadIdx.x;
    const int m0 = blockIdx.y * GTM;
    const int n0 = blockIdx.x * GTN;
    const int wid = tid >> 5, lane = tid & 31;
    const int g = lane >> 2, l = lane & 3;
    const int wm = (wid >> 1) * 32;
    const int wn = (wid & 1) * 64;

    float d[2][8][4];
#pragma unroll
    for (int mf = 0; mf < 2; mf++)
#pragma unroll
        for (int nf = 0; nf < 8; nf++)
#pragma unroll
            for (int q = 0; q < 4; q++) d[mf][nf][q] = 0.f;

    const int ar = tid >> 1, ac = (tid & 1) * 8, ac2 = (tid & 1) * 4;
    const float* Asrc = X + (size_t)(m0 + ar) * IN_ + ac;
    const bool bvalid = (n0 + ar) < G4H;
    const float* Bsrc = bvalid ? (Wih + (size_t)(n0 + ar) * IN_ + ac) : nullptr;

    for (int kt = 0; kt < IN_; kt += GTK) {
        __syncthreads();
        {
            float4 v0 = *(const float4*)(Asrc + kt);
            float4 v1 = *(const float4*)(Asrc + kt + 4);
            float av[8] = {v0.x,v0.y,v0.z,v0.w,v1.x,v1.y,v1.z,v1.w};
            float4 w0 = make_float4(0.f,0.f,0.f,0.f), w1 = w0;
            if (bvalid) { w0 = *(const float4*)(Bsrc + kt); w1 = *(const float4*)(Bsrc + kt + 4); }
            float bv[8] = {w0.x,w0.y,w0.z,w0.w,w1.x,w1.y,w1.z,w1.w};
#pragma unroll
            for (int p = 0; p < 4; p++) {
                __nv_bfloat162 h = __floats2bfloat162_rn(av[2*p], av[2*p+1]);
                float r0 = __bfloat162float(h.x), r1 = __bfloat162float(h.y);
                __nv_bfloat162 lo = __floats2bfloat162_rn(av[2*p] - r0, av[2*p+1] - r1);
                Ah[ac2 + p][ar] = *(const uint32_t*)&h;
                Al[ac2 + p][ar] = *(const uint32_t*)&lo;
                __nv_bfloat162 hb = __floats2bfloat162_rn(bv[2*p], bv[2*p+1]);
                float s0 = __bfloat162float(hb.x), s1 = __bfloat162float(hb.y);
                __nv_bfloat162 lb = __floats2bfloat162_rn(bv[2*p] - s0, bv[2*p+1] - s1);
                Bh[ac2 + p][ar] = *(const uint32_t*)&hb;
                Bl[ac2 + p][ar] = *(const uint32_t*)&lb;
            }
        }
        __syncthreads();

        uint32_t ah[2][4], al_[2][4];
#pragma unroll
        for (int mf = 0; mf < 2; mf++) {
            int base = wm + 16 * mf;
            ah[mf][0]  = Ah[l][base + g];
            ah[mf][1]  = Ah[l][base + g + 8];
            ah[mf][2]  = Ah[l + 4][base + g];
            ah[mf][3]  = Ah[l + 4][base + g + 8];
            al_[mf][0] = Al[l][base + g];
            al_[mf][1] = Al[l][base + g + 8];
            al_[mf][2] = Al[l + 4][base + g];
            al_[mf][3] = Al[l + 4][base + g + 8];
        }
#pragma unroll
        for (int nf = 0; nf < 8; nf++) {
            int nb = wn + 8 * nf;
            uint32_t bh0 = Bh[l][nb + g];
            uint32_t bh1 = Bh[l + 4][nb + g];
            uint32_t bl0 = Bl[l][nb + g];
            uint32_t bl1 = Bl[l + 4][nb + g];
#pragma unroll
            for (int mf = 0; mf < 2; mf++) {
                MMA_BF16(d[mf][nf], ah[mf],  bh0, bh1);
                MMA_BF16(d[mf][nf], al_[mf], bh0, bh1);
                MMA_BF16(d[mf][nf], ah[mf],  bl0, bl1);
            }
        }
    }

#pragma unroll
    for (int mf = 0; mf < 2; mf++) {
#pragma unroll
        for (int nf = 0; nf < 8; nf++) {
            int col = n0 + wn + 8 * nf + 2 * l;
            if (col < G4H) {
                float b0 = bih[col], b1 = bih[col + 1];
                int row0 = m0 + wm + 16 * mf + g;
                float2 o0 = make_float2(d[mf][nf][0] + b0, d[mf][nf][1] + b1);
                float2 o1 = make_float2(d[mf][nf][2] + b0, d[mf][nf][3] + b1);
                *(float2*)&g_G[(size_t)row0 * G4H + col]       = o0;
                *(float2*)&g_G[(size_t)(row0 + 8) * G4H + col] = o1;
            }
        }
    }
}

// ---------------- recurrent kernel (R13 base + Wka pin + p2 prefetch) ----------------
struct __align__(16) BS {
    float M[N_ * MSTRIDE];
    float r[RD];
    float key[RD];
    float add[RD];
    float wr[R_ * N_];
    float wu[N_];
    float wwsum[N_];
    float Ksm[R_ * N_];
    float m2[N_];
    float wlu[N_];
    float outh[NCLS];
    float key2[R_];
    float sig;
    float pad_[2];
};
#define BSF (sizeof(BS)/4)

#define OFF_SWRH   (2*BSF)
#define OFF_HPRE   (OFF_SWRH + 8000)
#define OFF_HT     (OFF_HPRE + 1600)
#define OFF_RALL   (OFF_HT   + 1600)
#define OFF_CSL    (OFF_RALL + 1312)
#define OFF_PBUF   (OFF_CSL  + 400)
#define OFF_SWKA   (OFF_PBUF + 12800)   // float2[k=200][j=40] = 16000 floats (64 KB)
#define SMEM_FLOATS (OFF_SWKA + 16000)

__device__ __forceinline__ float sigmoidf_(float x) { return 1.f / (1.f + expf(-x)); }

__global__ __launch_bounds__(THREADS) __cluster_dims__(CS, 1, 1)
void mann_recurrent(
    const float* __restrict__ bkey, const float* __restrict__ badd,
    const float* __restrict__ Wsig, const float* __restrict__ bsig,
    const float* __restrict__ Who,  const float* __restrict__ bho,
    const float* __restrict__ Wro,  const float* __restrict__ bro,
    const float* __restrict__ brh,  const float* __restrict__ bhh,
    float* __restrict__ out) {
    extern __shared__ float smemf[];
    BS* S          = reinterpret_cast<BS*>(smemf);
    float* sWrh    = smemf + OFF_SWRH;
    float* hpreAll = smemf + OFF_HPRE;
    float* htAll   = smemf + OFF_HT;
    float* rAll    = smemf + OFF_RALL;
    float* cSlice  = smemf + OFF_CSL;
    float* Pbuf    = smemf + OFF_PBUF;
    float2* sWka   = reinterpret_cast<float2*>(smemf + OFF_SWKA);

    const int tid  = threadIdx.x;
    const int blk  = blockIdx.x;
    const int wid  = tid >> 5, lane = tid & 31;
    const unsigned rank = ctarank();
    const int bbase = (blk >> 2) * 8;

    for (int b = 0; b < BPB; b++) {
        BS& s = S[b];
        for (int i = tid; i < N_ * MSTRIDE; i += THREADS) s.M[i] = 0.f;
        for (int i = tid; i < RD; i += THREADS) s.r[i] = 0.f;
        for (int i = tid; i < R_ * N_; i += THREADS) s.wr[i] = 0.f;
        for (int i = tid; i < N_; i += THREADS) s.wu[i] = 0.f;
    }
    for (int i = tid; i < 8 * 200; i += THREADS) htAll[i] = 0.f;
    for (int i = tid; i < 8 * RSTR; i += THREADS) rAll[i] = 0.f;
    for (int i = tid; i < 8 * 50; i += THREADS) cSlice[i] = 0.f;
    for (int idx = tid; idx < 160 * 50; idx += THREADS) {
        int k = idx / 50, i = idx % 50;
        sWrh[idx] = g_WrhT[k * 200 + 50 * rank + i];
    }
    // pin this CTA's key/add weight slice in SMEM (64 KB)
    for (int idx = tid; idx < 200 * 40; idx += THREADS) {
        int k = idx / 40, j = idx % 40;
        sWka[idx] = *(const float2*)&g_Wka2[k * 320 + (40 * rank + j) * 2];
    }
    __syncthreads();
    CLUSTER_SYNC();

    const int p_b = tid & 7;
    const int p_i = tid >> 3;
    const int jg1 = 50 * rank + ((p_i < 50) ? p_i : 0);
    const float brh_r = brh[jg1];
    const int ci = tid % 50;
    const int cb = tid / 50;
    const int jg = 50 * rank + ci;
    float bh0 = bhh[jg], bh1 = bhh[200 + jg], bh2 = bhh[400 + jg], bh3 = bhh[600 + jg];
    const int fj = tid % 40;
    const int fb = tid / 40;
    const int jgka = 40 * rank + fj;
    const float bkey_r = bkey[jgka], badd_r = badd[jgka];
    // p2 GEMV mapping (hoisted)
    const int i2 = tid % 50;
    const int ks2 = tid / 50;                 // 0..7 valid when tid<400
    const int k0p = 25 * ((ks2 < 8) ? ks2 : 0);
    const float4* Wp2 = reinterpret_cast<const float4*>(g_Wg4) + (50 * rank + i2);

    for (int t = 0; t < T_; t++) {
        float G0 = 0.f, G1 = 0.f, G2 = 0.f, G3 = 0.f;
        float4 wpre[8];
        if (tid < 400) {
            const float* Gp = g_G + ((size_t)(bbase + cb) * T_ + t) * G4H;
            G0 = Gp[jg]; G1 = Gp[200 + jg]; G2 = Gp[400 + jg]; G3 = Gp[600 + jg];
            // prefetch first 8 Wg4 float4s for this step's p2 (independent of h)
#pragma unroll
            for (int kk = 0; kk < 8; kk++) wpre[kk] = Wp2[(k0p + kk) * 200];
        }

        // ---- phase 1: hpre GEMV | LRU | prev output ----
        if (tid < 400) {
            const float* rr = &rAll[p_b * RSTR];
            float acc = htAll[p_b * 200 + jg1] + brh_r;
#pragma unroll 8
            for (int k = 0; k < RD; k++) acc += rr[k] * sWrh[k * 50 + p_i];
            bcast_all(&hpreAll[p_b * 200 + jg1], acc);
        } else if (wid == 13 || wid == 14) {
            int b = wid - 13;
            unsigned long long kv[4];
            float wl[4];
#pragma unroll
            for (int q = 0; q < 4; q++) {
                int n = lane + 32 * q;
                unsigned u = __float_as_uint(S[b].wu[n]);
                u = (u & 0x80000000u) ? ~u : (u | 0x80000000u);
                kv[q] = ((unsigned long long)u << 32) | (unsigned)n;
                wl[q] = 0.f;
            }
#pragma unroll
            for (int ss = 0; ss < 4; ss++) {
                unsigned long long m = kv[0]; int qi = 0;
#pragma unroll
                for (int q = 1; q < 4; q++) if (kv[q] < m) { m = kv[q]; qi = q; }
                unsigned long long wm = m;
#pragma unroll
                for (int o = 16; o > 0; o >>= 1) {
                    unsigned long long x = __shfl_xor_sync(0xffffffffu, wm, o);
                    if (x < wm) wm = x;
                }
                if (m == wm) { wl[qi] = 1.f; kv[qi] = ~0ull; }
            }
#pragma unroll
            for (int q = 0; q < 4; q++) S[b].wlu[lane + 32 * q] = wl[q];
        } else if (wid == 15 && t > 0) {
            for (int p = 0; p < BPB * NCLS; p++) {
                int b = p / NCLS, cls = p % NCLS;
                const float* rr = S[b].r;
                float acc = 0.f;
#pragma unroll
                for (int k = lane; k < RD; k += 32) acc += rr[k] * Wro[cls * RD + k];
#pragma unroll
                for (int o = 16; o > 0; o >>= 1) acc += __shfl_down_sync(0xffffffffu, acc, o);
                if (lane == 0)
                    out[((size_t)(blk * BPB + b) * T_ + (t - 1)) * NCLS + cls] = acc + S[b].outh[cls];
            }
        }
        CLUSTER_SYNC();

        // ---- phase 2 GEMV: gates slice (first 8 k pre-staged in registers) ----
        if (tid < 400) {
            float ag[8][4];
#pragma unroll
            for (int b = 0; b < 8; b++)
#pragma unroll
                for (int g = 0; g < 4; g++) ag[b][g] = 0.f;
#pragma unroll
            for (int kk = 0; kk < 8; kk++) {
                int k = k0p + kk;
                float4 w = wpre[kk];
#pragma unroll
                for (int b = 0; b < 8; b++) {
                    float hb = hpreAll[b * 200 + k];
                    ag[b][0] += w.x * hb; ag[b][1] += w.y * hb;
                    ag[b][2] += w.z * hb; ag[b][3] += w.w * hb;
                }
            }
#pragma unroll 5
            for (int kk = 8; kk < 25; kk++) {
                int k = k0p + kk;
                float4 w = Wp2[k * 200];
#pragma unroll
                for (int b = 0; b < 8; b++) {
                    float hb = hpreAll[b * 200 + k];
                    ag[b][0] += w.x * hb; ag[b][1] += w.y * hb;
                    ag[b][2] += w.z * hb; ag[b][3] += w.w * hb;
                }
            }
#pragma unroll
            for (int b = 0; b < 8; b++)
#pragma unroll
                for (int g = 0; g < 4; g++)
                    Pbuf[(b * 4 + g) * 400 + ks2 * 50 + i2] = ag[b][g];
        }
        __syncthreads();

        // ---- phase 2b: combine + LSTM + h_t broadcast ----
        if (tid < 400) {
            float s0 = G0 + bh0, s1 = G1 + bh1, s2 = G2 + bh2, s3 = G3 + bh3;
#pragma unroll
            for (int ks = 0; ks < 8; ks++) {
                s0 += Pbuf[(cb * 4 + 0) * 400 + ks * 50 + ci];
                s1 += Pbuf[(cb * 4 + 1) * 400 + ks * 50 + ci];
                s2 += Pbuf[(cb * 4 + 2) * 400 + ks * 50 + ci];
                s3 += Pbuf[(cb * 4 + 3) * 400 + ks * 50 + ci];
            }
            float ig = sigmoidf_(s0), fg = sigmoidf_(s1);
            float gg = tanhf(s2),    og = sigmoidf_(s3);
            float ct = fg * cSlice[cb * 50 + ci] + ig * gg;
            cSlice[cb * 50 + ci] = ct;
            float ht = og * tanhf(ct);
            bcast_all(&htAll[cb * 200 + jg], ht);
        }
        CLUSTER_SYNC();

        // ---- phase 4 GEMV: key/add slice (SMEM weights) | sigma | outh ----
        if (tid < 320) {
            int j = tid % 40, ks = tid / 40;
            float ak[8], aa[8];
#pragma unroll
            for (int b = 0; b < 8; b++) { ak[b] = 0.f; aa[b] = 0.f; }
            int k0 = 25 * ks;
#pragma unroll 5
            for (int kk = 0; kk < 25; kk++) {
                int k = k0 + kk;
                float2 w = sWka[k * 40 + j];
#pragma unroll
                for (int b = 0; b < 8; b++) {
                    float hb = htAll[b * 200 + k];
                    ak[b] += w.x * hb; aa[b] += w.y * hb;
                }
            }
#pragma unroll
            for (int b = 0; b < 8; b++) {
                Pbuf[(b * 2 + 0) * 320 + ks * 40 + j] = ak[b];
                Pbuf[(b * 2 + 1) * 320 + ks * 40 + j] = aa[b];
            }
        } else if (wid == 10 || wid == 11) {
            int b = wid - 10;
            const float* hh = &htAll[(rank * 2 + b) * 200];
            float p = 0.f;
            for (int k = lane; k < H_; k += 32) p += hh[k] * Wsig[k];
#pragma unroll
            for (int o = 16; o > 0; o >>= 1) p += __shfl_xor_sync(0xffffffffu, p, o);
            if (lane == 0) S[b].sig = p + bsig[0];
        } else if (wid == 12 || wid == 13) {
            int b = wid - 12;
            const float* hh = &htAll[(rank * 2 + b) * 200];
            for (int cls = 0; cls < NCLS; cls++) {
                float acc = 0.f;
#pragma unroll
                for (int k = lane; k < H_; k += 32) acc += hh[k] * Who[cls * H_ + k];
#pragma unroll
                for (int o = 16; o > 0; o >>= 1) acc += __shfl_down_sync(0xffffffffu, acc, o);
                if (lane == 0) S[b].outh[cls] = acc + bho[cls] + bro[cls];
            }
        }
        __syncthreads();

        // ---- phase 4b: combine + scatter key/add to owners ----
        if (tid < 320) {
            float vk = bkey_r, va = badd_r;
#pragma unroll
            for (int ks = 0; ks < 8; ks++) {
                vk += Pbuf[(fb * 2 + 0) * 320 + ks * 40 + fj];
                va += Pbuf[(fb * 2 + 1) * 320 + ks * 40 + fj];
            }
            int owner = fb >> 1, lb = fb & 1;
            st_rank(&S[lb].key[jgka], vk, owner);
            st_rank(&S[lb].add[jgka], va, owner);
        }
        CLUSTER_SYNC();

        // ---- phase 6: M update + wwsum + m2 ; key2 ----
        {
            int b = tid >> 8;
            int n = (tid >> 1) & 127;
            int dh = tid & 1;
            BS& s = S[b];
            float sg = s.sig, omsg = 1.f - sg;
            float wl = s.wlu[n];
            float w0 = sg * s.wr[n]       + omsg * wl;
            float w1 = sg * s.wr[128 + n] + omsg * wl;
            float w2 = sg * s.wr[256 + n] + omsg * wl;
            float w3 = sg * s.wr[384 + n] + omsg * wl;
            if (dh == 0) s.wwsum[n] = w0 + w1 + w2 + w3;
            float m2p = 0.f;
            int d0 = dh * 20;
#pragma unroll
            for (int dd = 0; dd < 20; dd++) {
                int d = d0 + dd;
                float mv = s.M[n * MSTRIDE + d] * wl
                         + w0 * s.add[d] + w1 * s.add[40 + d]
                         + w2 * s.add[80 + d] + w3 * s.add[120 + d];
                s.M[n * MSTRIDE + d] = mv;
                m2p += mv * mv;
            }
            m2p += __shfl_xor_sync(0xffffffffu, m2p, 1);
            if (dh == 0) s.m2[n] = m2p;
        }
        if (tid < 8) {
            int b = tid >> 2, r = tid & 3;
            float sum = 0.f;
#pragma unroll
            for (int d = 0; d < D_; d++) { float v = S[b].key[r * 40 + d]; sum += v * v; }
            S[b].key2[r] = sum;
        }
        __syncthreads();

        // ---- phase 7: cosine similarity ----
        for (int e = tid; e < 1024; e += THREADS) {
            int b = e >> 9, rn = e & 511, r = rn >> 7, n = rn & 127;
            BS& s = S[b];
            const float* kp = s.key + r * 40;
            const float* mp = s.M + n * MSTRIDE;
            float dot = 0.f;
#pragma unroll
            for (int d = 0; d < D_; d++) dot += kp[d] * mp[d];
            s.Ksm[rn] = dot / sqrtf(s.key2[r] * s.m2[n] + 1e-6f);
        }
        __syncthreads();

        // ---- phase 8: softmax over n (warp per (b,r)) ----
        if (wid < 8) {
            int b = wid >> 2, r = wid & 3;
            BS& s = S[b];
            float v0 = s.Ksm[r * N_ + lane];
            float v1 = s.Ksm[r * N_ + 32 + lane];
            float v2 = s.Ksm[r * N_ + 64 + lane];
            float v3 = s.Ksm[r * N_ + 96 + lane];
            float mx = fmaxf(fmaxf(v0, v1), fmaxf(v2, v3));
#pragma unroll
            for (int o = 16; o > 0; o >>= 1) mx = fmaxf(mx, __shfl_xor_sync(0xffffffffu, mx, o));
            float e0 = expf(v0 - mx), e1 = expf(v1 - mx), e2 = expf(v2 - mx), e3 = expf(v3 - mx);
            float su = e0 + e1 + e2 + e3;
#pragma unroll
            for (int o = 16; o > 0; o >>= 1) su += __shfl_xor_sync(0xffffffffu, su, o);
            float inv = 1.f / su;
            s.wr[r * N_ + lane]      = e0 * inv;
            s.wr[r * N_ + 32 + lane] = e1 * inv;
            s.wr[r * N_ + 64 + lane] = e2 * inv;
            s.wr[r * N_ + 96 + lane] = e3 * inv;
        }
        __syncthreads();

        // ---- phase 9: wu update ; phase 10: r_t = wr @ M + broadcast ----
        if (tid < 256) {
            int b = tid >> 7, n = tid & 127;
            BS& s = S[b];
            s.wu[n] = 0.95f * s.wu[n]
                    + (s.wr[n] + s.wr[128 + n] + s.wr[256 + n] + s.wr[384 + n])
                    + s.wwsum[n];
        }
        if (tid < 320) {
            int b = tid / 160, rd = tid % 160;
            int r = rd / 40, d = rd % 40;
            BS& s = S[b];
            const float* wrp = s.wr + r * N_;
            float dot = 0.f;
#pragma unroll 8
            for (int n = 0; n < N_; n++) dot += wrp[n] * s.M[n * MSTRIDE + d];
            s.r[rd] = dot;
            bcast_all(&rAll[(rank * 2 + b) * RSTR + rd], dot);
        }
        CLUSTER_SYNC();
    }

    // ---- final output (t = 99) ----
    if (wid == 15) {
        for (int p = 0; p < BPB * NCLS; p++) {
            int b = p / NCLS, cls = p % NCLS;
            const float* rr = S[b].r;
            float acc = 0.f;
#pragma unroll
            for (int k = lane; k < RD; k += 32) acc += rr[k] * Wro[cls * RD + k];
#pragma unroll
            for (int o = 16; o > 0; o >>= 1) acc += __shfl_down_sync(0xffffffffu, acc, o);
            if (lane == 0)
                out[((size_t)(blk * BPB + b) * T_ + (T_ - 1)) * NCLS + cls] = acc + S[b].outh[cls];
        }
    }
}

// ---------------- launch ----------------
extern "C" void kernel_launch(void* const* d_in, const int* in_sizes, int n_in,
                              void* d_out, int out_size) {
    const float* x    = (const float*)d_in[0];
    const float* Wkey = (const float*)d_in[1];
    const float* bkey = (const float*)d_in[2];
    const float* Wadd = (const float*)d_in[3];
    const float* badd = (const float*)d_in[4];
    const float* Wsig = (const float*)d_in[5];
    const float* bsig = (const float*)d_in[6];
    const float* Who  = (const float*)d_in[7];
    const float* bho  = (const float*)d_in[8];
    const float* Wro  = (const float*)d_in[9];
    const float* bro  = (const float*)d_in[10];
    const float* Wrh  = (const float*)d_in[11];
    const float* brh  = (const float*)d_in[12];
    const float* Wih  = (const float*)d_in[13];
    const float* bih  = (const float*)d_in[14];
    const float* Whh  = (const float*)d_in[15];
    const float* bhh  = (const float*)d_in[16];
    float* out = (float*)d_out;

    prep_weights<<<1000, 256>>>(Whh, Wkey, Wadd, Wrh);
    gemm_gates_x<<<dim3((G4H + GTN - 1) / GTN, B_ * T_ / GTM), 256>>>(x, Wih, bih);

    size_t shmem = (size_t)SMEM_FLOATS * 4;
    cudaFuncSetAttribute(mann_recurrent, cudaFuncAttributeMaxDynamicSharedMemorySize, (int)shmem);
    mann_recurrent<<<NBLK, THREADS, shmem>>>(bkey, badd, Wsig, bsig, Who, bho,
                                             Wro, bro, brh, bhh, out);
}

// round 16
// speedup vs baseline: 1.0504x; 1.0394x over previous
#include <cuda_runtime.h>
#include <cuda_bf16.h>
#include <math.h>
#include <stdint.h>

#define B_    256
#define T_    100
#define IN_   784
#define H_    200
#define R_    4
#define N_    128
#define D_    40
#define NCLS  5
#define G4H   800
#define RD    160
#define MSTRIDE 41
#define RSTR  164

#define BPB   1
#define NBLK  (B_/BPB)     // 256 CTAs
#define THREADS 512
#define CS    4            // cluster covers 4 batch elements (1 per CTA)

// ---------------- device scratch ----------------
__device__ float g_G[B_*T_*G4H];
__device__ float g_Wg4[H_*H_*4];
__device__ float g_Wka2[H_*RD*2];
__device__ float g_WrhT[RD*H_];

// ---------------- cluster helpers ----------------
__device__ __forceinline__ unsigned ctarank() {
    unsigned r; asm("mov.u32 %0, %%cluster_ctarank;" : "=r"(r)); return r;
}
__device__ __forceinline__ void bcast_all(void* p, float v) {
    unsigned a = (unsigned)__cvta_generic_to_shared(p);
#pragma unroll
    for (int r = 0; r < CS; r++) {
        unsigned ra;
        asm("mapa.shared::cluster.u32 %0, %1, %2;" : "=r"(ra) : "r"(a), "r"(r));
        asm volatile("st.shared::cluster.f32 [%0], %1;" :: "r"(ra), "f"(v));
    }
}
__device__ __forceinline__ void st_rank(void* p, float v, int r) {
    unsigned a = (unsigned)__cvta_generic_to_shared(p);
    unsigned ra;
    asm("mapa.shared::cluster.u32 %0, %1, %2;" : "=r"(ra) : "r"(a), "r"(r));
    asm volatile("st.shared::cluster.f32 [%0], %1;" :: "r"(ra), "f"(v));
}
#define CLUSTER_SYNC() do { \
    asm volatile("barrier.cluster.arrive.aligned;" ::: "memory"); \
    asm volatile("barrier.cluster.wait.aligned;"   ::: "memory"); \
} while (0)

// ---------------- weight repack ----------------
__global__ void prep_weights(const float* __restrict__ Whh,
                             const float* __restrict__ Wkey,
                             const float* __restrict__ Wadd,
                             const float* __restrict__ Wrh) {
    int i = blockIdx.x * 256 + threadIdx.x;
    if (i < 160000) {
        int k = i / 800, rem = i % 800, ii = rem >> 2, g = rem & 3;
        g_Wg4[i] = Whh[(g * 200 + ii) * 200 + k];
    } else if (i < 224000) {
        int z = i - 160000;
        int k = z / 320, rem = z % 320, j = rem >> 1, w = rem & 1;
        g_Wka2[z] = w ? Wadd[j * 200 + k] : Wkey[j * 200 + k];
    } else if (i < 256000) {
        int z = i - 224000; int k = z / 200, j = z % 200;
        g_WrhT[z] = Wrh[j * 160 + k];
    }
}

// ---------------- big input GEMM (R13, byte-identical): bf16 split-3 m16n8k16 ----------------
#define GTM 128
#define GTN 128
#define GTK 16
#define GSTR 136

#define MMA_BF16(D, A, B0, B1) \
    asm volatile("mma.sync.aligned.m16n8k16.row.col.f32.bf16.bf16.f32 " \
                 "{%0,%1,%2,%3}, {%4,%5,%6,%7}, {%8,%9}, {%0,%1,%2,%3};" \
                 : "+f"((D)[0]), "+f"((D)[1]), "+f"((D)[2]), "+f"((D)[3]) \
                 : "r"((A)[0]), "r"((A)[1]), "r"((A)[2]), "r"((A)[3]), \
                   "r"(B0), "r"(B1))

__global__ __launch_bounds__(256) void gemm_gates_x(
    const float* __restrict__ X, const float* __restrict__ Wih,
    const float* __restrict__ bih) {
    __shared__ uint32_t Ah[8][GSTR], Al[8][GSTR];
    __shared__ uint32_t Bh[8][GSTR], Bl[8][GSTR];

    const int tid = threadIdx.x;
    const int m0 = blockIdx.y * GTM;
    const int n0 = blockIdx.x * GTN;
    const int wid = tid >> 5, lane = tid & 31;
    const int g = lane >> 2, l = lane & 3;
    const int wm = (wid >> 1) * 32;
    const int wn = (wid & 1) * 64;

    float d[2][8][4];
#pragma unroll
    for (int mf = 0; mf < 2; mf++)
#pragma unroll
        for (int nf = 0; nf < 8; nf++)
#pragma unroll
            for (int q = 0; q < 4; q++) d[mf][nf][q] = 0.f;

    const int ar = tid >> 1, ac = (tid & 1) * 8, ac2 = (tid & 1) * 4;
    const float* Asrc = X + (size_t)(m0 + ar) * IN_ + ac;
    const bool bvalid = (n0 + ar) < G4H;
    const float* Bsrc = bvalid ? (Wih + (size_t)(n0 + ar) * IN_ + ac) : nullptr;

    for (int kt = 0; kt < IN_; kt += GTK) {
        __syncthreads();
        {
            float4 v0 = *(const float4*)(Asrc + kt);
            float4 v1 = *(const float4*)(Asrc + kt + 4);
            float av[8] = {v0.x,v0.y,v0.z,v0.w,v1.x,v1.y,v1.z,v1.w};
            float4 w0 = make_float4(0.f,0.f,0.f,0.f), w1 = w0;
            if (bvalid) { w0 = *(const float4*)(Bsrc + kt); w1 = *(const float4*)(Bsrc + kt + 4); }
            float bv[8] = {w0.x,w0.y,w0.z,w0.w,w1.x,w1.y,w1.z,w1.w};
#pragma unroll
            for (int p = 0; p < 4; p++) {
                __nv_bfloat162 h = __floats2bfloat162_rn(av[2*p], av[2*p+1]);
                float r0 = __bfloat162float(h.x), r1 = __bfloat162float(h.y);
                __nv_bfloat162 lo = __floats2bfloat162_rn(av[2*p] - r0, av[2*p+1] - r1);
                Ah[ac2 + p][ar] = *(const uint32_t*)&h;
                Al[ac2 + p][ar] = *(const uint32_t*)&lo;
                __nv_bfloat162 hb = __floats2bfloat162_rn(bv[2*p], bv[2*p+1]);
                float s0 = __bfloat162float(hb.x), s1 = __bfloat162float(hb.y);
                __nv_bfloat162 lb = __floats2bfloat162_rn(bv[2*p] - s0, bv[2*p+1] - s1);
                Bh[ac2 + p][ar] = *(const uint32_t*)&hb;
                Bl[ac2 + p][ar] = *(const uint32_t*)&lb;
            }
        }
        __syncthreads();

        uint32_t ah[2][4], al_[2][4];
#pragma unroll
        for (int mf = 0; mf < 2; mf++) {
            int base = wm + 16 * mf;
            ah[mf][0]  = Ah[l][base + g];
            ah[mf][1]  = Ah[l][base + g + 8];
            ah[mf][2]  = Ah[l + 4][base + g];
            ah[mf][3]  = Ah[l + 4][base + g + 8];
            al_[mf][0] = Al[l][base + g];
            al_[mf][1] = Al[l][base + g + 8];
            al_[mf][2] = Al[l + 4][base + g];
            al_[mf][3] = Al[l + 4][base + g + 8];
        }
#pragma unroll
        for (int nf = 0; nf < 8; nf++) {
            int nb = wn + 8 * nf;
            uint32_t bh0 = Bh[l][nb + g];
            uint32_t bh1 = Bh[l + 4][nb + g];
            uint32_t bl0 = Bl[l][nb + g];
            uint32_t bl1 = Bl[l + 4][nb + g];
#pragma unroll
            for (int mf = 0; mf < 2; mf++) {
                MMA_BF16(d[mf][nf], ah[mf],  bh0, bh1);
                MMA_BF16(d[mf][nf], al_[mf], bh0, bh1);
                MMA_BF16(d[mf][nf], ah[mf],  bl0, bl1);
            }
        }
    }

#pragma unroll
    for (int mf = 0; mf < 2; mf++) {
#pragma unroll
        for (int nf = 0; nf < 8; nf++) {
            int col = n0 + wn + 8 * nf + 2 * l;
            if (col < G4H) {
                float b0 = bih[col], b1 = bih[col + 1];
                int row0 = m0 + wm + 16 * mf + g;
                float2 o0 = make_float2(d[mf][nf][0] + b0, d[mf][nf][1] + b1);
                float2 o1 = make_float2(d[mf][nf][2] + b0, d[mf][nf][3] + b1);
                *(float2*)&g_G[(size_t)row0 * G4H + col]       = o0;
                *(float2*)&g_G[(size_t)(row0 + 8) * G4H + col] = o1;
            }
        }
    }
}

// ---------------- recurrent kernel: 1 batch/CTA, 2 CTAs/SM ----------------
struct __align__(16) BS {
    float M[N_ * MSTRIDE];
    float r[RD];
    float key[RD];
    float add[RD];
    float wr[R_ * N_];
    float wu[N_];
    float wwsum[N_];
    float Ksm[R_ * N_];
    float m2[N_];
    float wlu[N_];
    float outh[NCLS];
    float key2[R_];
    float sig;
    float pad_[2];
};
#define BSF (sizeof(BS)/4)

#define OFF_SWRH   (BSF)                 // sWrh [k=160][i=50]
#define OFF_HPRE   (OFF_SWRH + 8000)     // hpreAll [cb=4][200]
#define OFF_HT     (OFF_HPRE + 800)      // htAll [cb=4][200]
#define OFF_RALL   (OFF_HT   + 800)      // rAll [cb=4][RSTR]
#define OFF_CSL    (OFF_RALL + 656)      // cSlice [cb=4][50]
#define OFF_PBUF   (OFF_CSL  + 200)      // Pbuf 16*400 = 6400
#define SMEM_FLOATS (OFF_PBUF + 6400)    // 24132 floats = 96528 B -> 2 CTAs/SM

__device__ __forceinline__ float sigmoidf_(float x) { return 1.f / (1.f + expf(-x)); }

__global__ __launch_bounds__(THREADS, 2) __cluster_dims__(CS, 1, 1)
void mann_recurrent(
    const float* __restrict__ bkey, const float* __restrict__ badd,
    const float* __restrict__ Wsig, const float* __restrict__ bsig,
    const float* __restrict__ Who,  const float* __restrict__ bho,
    const float* __restrict__ Wro,  const float* __restrict__ bro,
    const float* __restrict__ brh,  const float* __restrict__ bhh,
    float* __restrict__ out) {
    extern __shared__ float smemf[];
    BS* S          = reinterpret_cast<BS*>(smemf);   // S[0] only
    float* sWrh    = smemf + OFF_SWRH;
    float* hpreAll = smemf + OFF_HPRE;
    float* htAll   = smemf + OFF_HT;
    float* rAll    = smemf + OFF_RALL;
    float* cSlice  = smemf + OFF_CSL;
    float* Pbuf    = smemf + OFF_PBUF;

    const int tid  = threadIdx.x;
    const int blk  = blockIdx.x;
    const int wid  = tid >> 5, lane = tid & 31;
    const unsigned rank = ctarank();
    const int bbase = (blk >> 2) * 4;     // cluster's first global batch index
    const int bown  = bbase + rank;       // this CTA's batch element

    {
        BS& s = S[0];
        for (int i = tid; i < N_ * MSTRIDE; i += THREADS) s.M[i] = 0.f;
        for (int i = tid; i < RD; i += THREADS) s.r[i] = 0.f;
        for (int i = tid; i < R_ * N_; i += THREADS) s.wr[i] = 0.f;
        for (int i = tid; i < N_; i += THREADS) s.wu[i] = 0.f;
    }
    for (int i = tid; i < 4 * 200; i += THREADS) { htAll[i] = 0.f; }
    for (int i = tid; i < 4 * RSTR; i += THREADS) rAll[i] = 0.f;
    for (int i = tid; i < 4 * 50; i += THREADS) cSlice[i] = 0.f;
    for (int idx = tid; idx < 160 * 50; idx += THREADS) {
        int k = idx / 50, i = idx % 50;
        sWrh[idx] = g_WrhT[k * 200 + 50 * rank + i];
    }
    __syncthreads();
    CLUSTER_SYNC();

    // p1 mapping (tid < 200): p_b = tid%4, p_i = tid/4
    const int p_b = tid & 3;
    const int p_i = tid >> 2;                       // 0..49 valid when tid<200
    const int jg1 = 50 * rank + ((p_i < 50) ? p_i : 0);
    const float brh_r = brh[jg1];
    // p2b combine mapping (tid < 200): cb = tid/50, ci = tid%50
    const int ci = tid % 50;
    const int cb = (tid / 50) & 3;
    const int jg = 50 * rank + ci;
    const float bh0 = bhh[jg], bh1 = bhh[200 + jg], bh2 = bhh[400 + jg], bh3 = bhh[600 + jg];
    // p4b scatter mapping (tid < 160): fb = tid/40, fj = tid%40
    const int fj = tid % 40;
    const int fb = (tid / 40) & 3;
    const int jgka = 40 * rank + fj;
    const float bkey_r = bkey[jgka], badd_r = badd[jgka];
    // p2 GEMV mapping (tid < 400): ks2 = tid/50 (0..7), i2 = tid%50
    const int i2 = tid % 50;
    const int ks2 = (tid / 50) & 7;
    const float4* Wp2 = reinterpret_cast<const float4*>(g_Wg4) + (50 * rank + i2);

    for (int t = 0; t < T_; t++) {
        float G0 = 0.f, G1 = 0.f, G2 = 0.f, G3 = 0.f;
        if (tid < 200) {
            const float* Gp = g_G + ((size_t)(bbase + cb) * T_ + t) * G4H;
            G0 = Gp[jg]; G1 = Gp[200 + jg]; G2 = Gp[400 + jg]; G3 = Gp[600 + jg];
        }

        // ---- phase 1: hpre slice GEMV (4 b x 50 i) | LRU | prev output ----
        if (tid < 200) {
            const float* rr = &rAll[p_b * RSTR];
            float acc = htAll[p_b * 200 + jg1] + brh_r;
#pragma unroll 8
            for (int k = 0; k < RD; k++) acc += rr[k] * sWrh[k * 50 + p_i];
            bcast_all(&hpreAll[p_b * 200 + jg1], acc);
        } else if (wid == 13) {
            // stable 4-smallest of wu (own batch only)
            BS& s = S[0];
            unsigned long long kv[4];
            float wl[4];
#pragma unroll
            for (int q = 0; q < 4; q++) {
                int n = lane + 32 * q;
                unsigned u = __float_as_uint(s.wu[n]);
                u = (u & 0x80000000u) ? ~u : (u | 0x80000000u);
                kv[q] = ((unsigned long long)u << 32) | (unsigned)n;
                wl[q] = 0.f;
            }
#pragma unroll
            for (int ss = 0; ss < 4; ss++) {
                unsigned long long m = kv[0]; int qi = 0;
#pragma unroll
                for (int q = 1; q < 4; q++) if (kv[q] < m) { m = kv[q]; qi = q; }
                unsigned long long wm = m;
#pragma unroll
                for (int o = 16; o > 0; o >>= 1) {
                    unsigned long long x = __shfl_xor_sync(0xffffffffu, wm, o);
                    if (x < wm) wm = x;
                }
                if (m == wm) { wl[qi] = 1.f; kv[qi] = ~0ull; }
            }
#pragma unroll
            for (int q = 0; q < 4; q++) s.wlu[lane + 32 * q] = wl[q];
        } else if (wid == 15 && t > 0) {
            const float* rr = S[0].r;
            for (int cls = 0; cls < NCLS; cls++) {
                float acc = 0.f;
#pragma unroll
                for (int k = lane; k < RD; k += 32) acc += rr[k] * Wro[cls * RD + k];
#pragma unroll
                for (int o = 16; o > 0; o >>= 1) acc += __shfl_down_sync(0xffffffffu, acc, o);
                if (lane == 0)
                    out[((size_t)bown * T_ + (t - 1)) * NCLS + cls] = acc + S[0].outh[cls];
            }
        }
        CLUSTER_SYNC();

        // ---- phase 2 GEMV: gates slice for 4 b ----
        if (tid < 400) {
            float ag[4][4];
#pragma unroll
            for (int b = 0; b < 4; b++)
#pragma unroll
                for (int g = 0; g < 4; g++) ag[b][g] = 0.f;
            int k0 = 25 * ks2;
#pragma unroll 5
            for (int kk = 0; kk < 25; kk++) {
                int k = k0 + kk;
                float4 w = Wp2[k * 200];
#pragma unroll
                for (int b = 0; b < 4; b++) {
                    float hb = hpreAll[b * 200 + k];
                    ag[b][0] += w.x * hb; ag[b][1] += w.y * hb;
                    ag[b][2] += w.z * hb; ag[b][3] += w.w * hb;
                }
            }
#pragma unroll
            for (int b = 0; b < 4; b++)
#pragma unroll
                for (int g = 0; g < 4; g++)
                    Pbuf[(b * 4 + g) * 400 + ks2 * 50 + i2] = ag[b][g];
        }
        __syncthreads();

        // ---- phase 2b: combine + LSTM + h_t broadcast ----
        if (tid < 200) {
            float s0 = G0 + bh0, s1 = G1 + bh1, s2 = G2 + bh2, s3 = G3 + bh3;
#pragma unroll
            for (int ks = 0; ks < 8; ks++) {
                s0 += Pbuf[(cb * 4 + 0) * 400 + ks * 50 + ci];
                s1 += Pbuf[(cb * 4 + 1) * 400 + ks * 50 + ci];
                s2 += Pbuf[(cb * 4 + 2) * 400 + ks * 50 + ci];
                s3 += Pbuf[(cb * 4 + 3) * 400 + ks * 50 + ci];
            }
            float ig = sigmoidf_(s0), fg = sigmoidf_(s1);
            float gg = tanhf(s2),    og = sigmoidf_(s3);
            float ct = fg * cSlice[cb * 50 + ci] + ig * gg;
            cSlice[cb * 50 + ci] = ct;
            float ht = og * tanhf(ct);
            bcast_all(&htAll[cb * 200 + jg], ht);
        }
        CLUSTER_SYNC();

        // ---- phase 4 GEMV: key/add slice for 4 b | sigma | outh ----
        if (tid < 320) {
            int j = tid % 40, ks = tid / 40;
            float ak[4], aa[4];
#pragma unroll
            for (int b = 0; b < 4; b++) { ak[b] = 0.f; aa[b] = 0.f; }
            const float2* W = reinterpret_cast<const float2*>(g_Wka2) + (40 * rank + j);
            int k0 = 25 * ks;
#pragma unroll 5
            for (int kk = 0; kk < 25; kk++) {
                int k = k0 + kk;
                float2 w = W[k * 160];
#pragma unroll
                for (int b = 0; b < 4; b++) {
                    float hb = htAll[b * 200 + k];
                    ak[b] += w.x * hb; aa[b] += w.y * hb;
                }
            }
#pragma unroll
            for (int b = 0; b < 4; b++) {
                Pbuf[(b * 2 + 0) * 320 + ks * 40 + j] = ak[b];
                Pbuf[(b * 2 + 1) * 320 + ks * 40 + j] = aa[b];
            }
        } else if (wid == 11) {
            // sigma for own batch
            const float* hh = &htAll[rank * 200];
            float p = 0.f;
            for (int k = lane; k < H_; k += 32) p += hh[k] * Wsig[k];
#pragma unroll
            for (int o = 16; o > 0; o >>= 1) p += __shfl_xor_sync(0xffffffffu, p, o);
            if (lane == 0) S[0].sig = p + bsig[0];
        } else if (wid == 12) {
            // outh for own batch
            const float* hh = &htAll[rank * 200];
            for (int cls = 0; cls < NCLS; cls++) {
                float acc = 0.f;
#pragma unroll
                for (int k = lane; k < H_; k += 32) acc += hh[k] * Who[cls * H_ + k];
#pragma unroll
                for (int o = 16; o > 0; o >>= 1) acc += __shfl_down_sync(0xffffffffu, acc, o);
                if (lane == 0) S[0].outh[cls] = acc + bho[cls] + bro[cls];
            }
        }
        __syncthreads();

        // ---- phase 4b: combine + scatter key/add to owners ----
        if (tid < 160) {
            float vk = bkey_r, va = badd_r;
#pragma unroll
            for (int ks = 0; ks < 8; ks++) {
                vk += Pbuf[(fb * 2 + 0) * 320 + ks * 40 + fj];
                va += Pbuf[(fb * 2 + 1) * 320 + ks * 40 + fj];
            }
            st_rank(&S[0].key[jgka], vk, fb);
            st_rank(&S[0].add[jgka], va, fb);
        }
        CLUSTER_SYNC();

        // ---- phase 6: M update + wwsum + m2 ; key2 ----
        if (tid < 256) {
            int n = tid >> 1;
            int dh = tid & 1;
            BS& s = S[0];
            float sg = s.sig, omsg = 1.f - sg;
            float wl = s.wlu[n];
            float w0 = sg * s.wr[n]       + omsg * wl;
            float w1 = sg * s.wr[128 + n] + omsg * wl;
            float w2 = sg * s.wr[256 + n] + omsg * wl;
            float w3 = sg * s.wr[384 + n] + omsg * wl;
            if (dh == 0) s.wwsum[n] = w0 + w1 + w2 + w3;
            float m2p = 0.f;
            int d0 = dh * 20;
#pragma unroll
            for (int dd = 0; dd < 20; dd++) {
                int d = d0 + dd;
                float mv = s.M[n * MSTRIDE + d] * wl
                         + w0 * s.add[d] + w1 * s.add[40 + d]
                         + w2 * s.add[80 + d] + w3 * s.add[120 + d];
                s.M[n * MSTRIDE + d] = mv;
                m2p += mv * mv;
            }
            m2p += __shfl_xor_sync(0xffffffffu, m2p, 1);
            if (dh == 0) s.m2[n] = m2p;
        }
        if (tid < 4) {
            int r = tid;
            float sum = 0.f;
#pragma unroll
            for (int d = 0; d < D_; d++) { float v = S[0].key[r * 40 + d]; sum += v * v; }
            S[0].key2[r] = sum;
        }
        __syncthreads();

        // ---- phase 7: cosine similarity (512 elems, 1 per thread) ----
        {
            int r = tid >> 7, n = tid & 127;
            BS& s = S[0];
            const float* kp = s.key + r * 40;
            const float* mp = s.M + n * MSTRIDE;
            float dot = 0.f;
#pragma unroll
            for (int d = 0; d < D_; d++) dot += kp[d] * mp[d];
            s.Ksm[r * N_ + n] = dot / sqrtf(s.key2[r] * s.m2[n] + 1e-6f);
        }
        __syncthreads();

        // ---- phase 8: softmax over n (warp per r) ----
        if (wid < 4) {
            int r = wid;
            BS& s = S[0];
            float v0 = s.Ksm[r * N_ + lane];
            float v1 = s.Ksm[r * N_ + 32 + lane];
            float v2 = s.Ksm[r * N_ + 64 + lane];
            float v3 = s.Ksm[r * N_ + 96 + lane];
            float mx = fmaxf(fmaxf(v0, v1), fmaxf(v2, v3));
#pragma unroll
            for (int o = 16; o > 0; o >>= 1) mx = fmaxf(mx, __shfl_xor_sync(0xffffffffu, mx, o));
            float e0 = expf(v0 - mx), e1 = expf(v1 - mx), e2 = expf(v2 - mx), e3 = expf(v3 - mx);
            float su = e0 + e1 + e2 + e3;
#pragma unroll
            for (int o = 16; o > 0; o >>= 1) su += __shfl_xor_sync(0xffffffffu, su, o);
            float inv = 1.f / su;
            s.wr[r * N_ + lane]      = e0 * inv;
            s.wr[r * N_ + 32 + lane] = e1 * inv;
            s.wr[r * N_ + 64 + lane] = e2 * inv;
            s.wr[r * N_ + 96 + lane] = e3 * inv;
        }
        __syncthreads();

        // ---- phase 9: wu update ; phase 10: r_t = wr @ M + broadcast ----
        if (tid < 128) {
            int n = tid;
            BS& s = S[0];
            s.wu[n] = 0.95f * s.wu[n]
                    + (s.wr[n] + s.wr[128 + n] + s.wr[256 + n] + s.wr[384 + n])
                    + s.wwsum[n];
        }
        if (tid < 160) {
            int rd = tid;
            int r = rd / 40, d = rd % 40;
            BS& s = S[0];
            const float* wrp = s.wr + r * N_;
            float dot = 0.f;
#pragma unroll 8
            for (int n = 0; n < N_; n++) dot += wrp[n] * s.M[n * MSTRIDE + d];
            s.r[rd] = dot;
            bcast_all(&rAll[rank * RSTR + rd], dot);
        }
        CLUSTER_SYNC();
    }

    // ---- final output (t = 99) ----
    if (wid == 15) {
        const float* rr = S[0].r;
        for (int cls = 0; cls < NCLS; cls++) {
            float acc = 0.f;
#pragma unroll
            for (int k = lane; k < RD; k += 32) acc += rr[k] * Wro[cls * RD + k];
#pragma unroll
            for (int o = 16; o > 0; o >>= 1) acc += __shfl_down_sync(0xffffffffu, acc, o);
            if (lane == 0)
                out[((size_t)bown * T_ + (T_ - 1)) * NCLS + cls] = acc + S[0].outh[cls];
        }
    }
}

// ---------------- launch ----------------
extern "C" void kernel_launch(void* const* d_in, const int* in_sizes, int n_in,
                              void* d_out, int out_size) {
    const float* x    = (const float*)d_in[0];
    const float* Wkey = (const float*)d_in[1];
    const float* bkey = (const float*)d_in[2];
    const float* Wadd = (const float*)d_in[3];
    const float* badd = (const float*)d_in[4];
    const float* Wsig = (const float*)d_in[5];
    const float* bsig = (const float*)d_in[6];
    const float* Who  = (const float*)d_in[7];
    const float* bho  = (const float*)d_in[8];
    const float* Wro  = (const float*)d_in[9];
    const float* bro  = (const float*)d_in[10];
    const float* Wrh  = (const float*)d_in[11];
    const float* brh  = (const float*)d_in[12];
    const float* Wih  = (const float*)d_in[13];
    const float* bih  = (const float*)d_in[14];
    const float* Whh  = (const float*)d_in[15];
    const float* bhh  = (const float*)d_in[16];
    float* out = (float*)d_out;

    prep_weights<<<1000, 256>>>(Whh, Wkey, Wadd, Wrh);
    gemm_gates_x<<<dim3((G4H + GTN - 1) / GTN, B_ * T_ / GTM), 256>>>(x, Wih, bih);

    size_t shmem = (size_t)SMEM_FLOATS * 4;
    cudaFuncSetAttribute(mann_recurrent, cudaFuncAttributeMaxDynamicSharedMemorySize, (int)shmem);
    mann_recurrent<<<NBLK, THREADS, shmem>>>(bkey, badd, Wsig, bsig, Who, bho,
                                             Wro, bro, brh, bhh, out);
}